// round 4
// baseline (speedup 1.0000x reference)
#include <cuda_runtime.h>

#define BB   4
#define CC   256
#define HH   56
#define WWD  56
#define HWP  3136        // 56*56
#define CR   64
#define GG   16
#define KW   7
#define GK   784         // G*K*K
#define EPSV 1e-5f

// Scratch (no allocations allowed; static device globals)
__device__ float g_t[(size_t)BB * CR * HWP];   // 3.2 MB
__device__ float g_w[(size_t)BB * GK * HWP];   // 39.3 MB

// ---------------------------------------------------------------------------
// Kernel 1: t = relu(BN(W1 @ x + b1)).  GEMM M=12544(pixels), N=64, K=256.
// Block: 256 threads, tile BM=64 pixels x BN=64 outputs, BK=64.
// ---------------------------------------------------------------------------
__global__ __launch_bounds__(256) void gen_t_kernel(
    const float* __restrict__ x, const float* __restrict__ W1,
    const float* __restrict__ b1, const float* __restrict__ gamma,
    const float* __restrict__ beta, const float* __restrict__ mean,
    const float* __restrict__ var)
{
    __shared__ float Xs[64][65];   // [c][p]
    __shared__ float Ws[64][65];   // [c][o]
    const int m0 = blockIdx.x * 64;
    const int b  = m0 / HWP;
    const int p0 = m0 % HWP;       // tiles never straddle batches (3136 % 64 == 0)
    const int tid = threadIdx.x;
    const int tx = tid & 15;       // pixel group
    const int ty = tid >> 4;       // output group

    float acc[4][4] = {};

    for (int c0 = 0; c0 < CC; c0 += 64) {
        const int lp = tid & 63;
        const int lr = tid >> 6;
        #pragma unroll
        for (int r = lr; r < 64; r += 4)
            Xs[r][lp] = x[((size_t)b * CC + c0 + r) * HWP + p0 + lp];
        // Ws[kk][oo] = W1[oo*256 + c0 + kk]  (coalesced read, transposed store)
        const int lk = tid & 63;
        const int lo = tid >> 6;
        #pragma unroll
        for (int o = lo; o < 64; o += 4)
            Ws[lk][o] = W1[o * CC + c0 + lk];
        __syncthreads();

        #pragma unroll
        for (int k = 0; k < 64; k++) {
            float a[4], w[4];
            #pragma unroll
            for (int i = 0; i < 4; i++) a[i] = Xs[k][tx + 16 * i];
            #pragma unroll
            for (int j = 0; j < 4; j++) w[j] = Ws[k][ty + 16 * j];
            #pragma unroll
            for (int j = 0; j < 4; j++)
                #pragma unroll
                for (int i = 0; i < 4; i++)
                    acc[j][i] += a[i] * w[j];
        }
        __syncthreads();
    }

    #pragma unroll
    for (int j = 0; j < 4; j++) {
        const int o = ty + 16 * j;
        const float sc = gamma[o] * rsqrtf(var[o] + EPSV);
        const float sh = beta[o] - mean[o] * sc;
        const float bv = b1[o];
        #pragma unroll
        for (int i = 0; i < 4; i++) {
            float v = (acc[j][i] + bv) * sc + sh;
            v = fmaxf(v, 0.0f);
            g_t[((size_t)b * CR + o) * HWP + p0 + tx + 16 * i] = v;
        }
    }
}

// ---------------------------------------------------------------------------
// Kernel 2: w = W2 @ t + b2.  GEMM M=12544, N=784, K=64 (single K chunk).
// Block: 256 threads, tile BM=64 x BN=64.
// ---------------------------------------------------------------------------
__global__ __launch_bounds__(256) void gen_w_kernel(
    const float* __restrict__ W2, const float* __restrict__ b2)
{
    __shared__ float Ts[64][65];    // [k][p]
    __shared__ float W2s[64][65];   // [k][n]
    const int m0 = blockIdx.x * 64;
    const int b  = m0 / HWP;
    const int p0 = m0 % HWP;
    const int n0 = blockIdx.y * 64;
    const int tid = threadIdx.x;
    const int tx = tid & 15;
    const int ty = tid >> 4;

    {
        const int lp = tid & 63;
        const int lr = tid >> 6;
        #pragma unroll
        for (int r = lr; r < 64; r += 4)
            Ts[r][lp] = g_t[((size_t)b * CR + r) * HWP + p0 + lp];
        const int lo = tid & 63;
        const int ln = tid >> 6;
        #pragma unroll
        for (int n = ln; n < 64; n += 4) {
            const int gn = n0 + n;
            W2s[lo][n] = (gn < GK) ? W2[gn * CR + lo] : 0.0f;
        }
    }
    __syncthreads();

    float acc[4][4] = {};
    #pragma unroll
    for (int k = 0; k < 64; k++) {
        float a[4], w[4];
        #pragma unroll
        for (int i = 0; i < 4; i++) a[i] = Ts[k][tx + 16 * i];
        #pragma unroll
        for (int j = 0; j < 4; j++) w[j] = W2s[k][ty + 16 * j];
        #pragma unroll
        for (int j = 0; j < 4; j++)
            #pragma unroll
            for (int i = 0; i < 4; i++)
                acc[j][i] += a[i] * w[j];
    }

    #pragma unroll
    for (int j = 0; j < 4; j++) {
        const int n = n0 + ty + 16 * j;
        if (n < GK) {
            const float bv = b2[n];
            #pragma unroll
            for (int i = 0; i < 4; i++)
                g_w[((size_t)b * GK + n) * HWP + p0 + tx + 16 * i] = acc[j][i] + bv;
        }
    }
}

// ---------------------------------------------------------------------------
// Kernel 3: involution.  Thread = 4 consecutive w-pixels x 1 channel.
// out[b,c,h,w] = sum_{i,j} xpad[b,c,h+i-3,w+j-3] * g_w[b, (c/16)*49 + i*7+j, h, w]
// ---------------------------------------------------------------------------
__global__ __launch_bounds__(256) void inv_kernel(
    const float* __restrict__ x, float* __restrict__ out)
{
    const int q  = blockIdx.x * blockDim.x + threadIdx.x;
    const int wq = q % 14;
    const int h  = (q / 14) % HH;
    const int c  = (q / (14 * HH)) % CC;
    const int b  = q / (14 * HH * CC);
    if (b >= BB) return;

    const int g  = c >> 4;
    const int w0 = wq * 4;
    const float* xc = x + ((size_t)b * CC + c) * HWP;
    const float* wc = g_w + ((size_t)b * GK + g * 49) * HWP + h * WWD + w0;

    float acc0 = 0.f, acc1 = 0.f, acc2 = 0.f, acc3 = 0.f;

    #pragma unroll
    for (int i = 0; i < KW; i++) {
        const int r = h + i - 3;
        if (r < 0 || r >= HH) continue;   // zero padding row
        const float* xrp = xc + r * WWD;
        float xr[10];
        #pragma unroll
        for (int jj = 0; jj < 10; jj++) {
            const int col = w0 - 3 + jj;
            xr[jj] = (col >= 0 && col < WWD) ? xrp[col] : 0.0f;
        }
        #pragma unroll
        for (int j = 0; j < KW; j++) {
            const float4 wv = *(const float4*)(wc + (size_t)(i * 7 + j) * HWP);
            acc0 = fmaf(xr[j + 0], wv.x, acc0);
            acc1 = fmaf(xr[j + 1], wv.y, acc1);
            acc2 = fmaf(xr[j + 2], wv.z, acc2);
            acc3 = fmaf(xr[j + 3], wv.w, acc3);
        }
    }

    float4 o4 = make_float4(acc0, acc1, acc2, acc3);
    *(float4*)(out + ((size_t)b * CC + c) * HWP + h * WWD + w0) = o4;
}

// ---------------------------------------------------------------------------
extern "C" void kernel_launch(void* const* d_in, const int* in_sizes, int n_in,
                              void* d_out, int out_size)
{
    const float* x     = (const float*)d_in[0];
    const float* W1    = (const float*)d_in[1];
    const float* b1    = (const float*)d_in[2];
    const float* gamma = (const float*)d_in[3];
    const float* beta  = (const float*)d_in[4];
    const float* mean  = (const float*)d_in[5];
    const float* var   = (const float*)d_in[6];
    const float* W2    = (const float*)d_in[7];
    const float* b2    = (const float*)d_in[8];
    float* out = (float*)d_out;

    gen_t_kernel<<<196, 256>>>(x, W1, b1, gamma, beta, mean, var);  // 12544/64
    dim3 g2(196, 13);                                               // 13*64 >= 784
    gen_w_kernel<<<g2, 256>>>(W2, b2);
    inv_kernel<<<3136, 256>>>(x, out);                              // 4*256*56*14/256
}